// round 2
// baseline (speedup 1.0000x reference)
#include <cuda_runtime.h>

// ---------------------------------------------------------------------------
// DynamicDWConv: conv3x3(VALID)+lrelu -> conv3x3(VALID)+lrelu -> global avg
// pool -> 1x1 conv (per-sample depthwise 3x3 kernel gen) -> depthwise conv
// SAME + bias.
// B=16, C=256, H=W=64, K=3.
// ---------------------------------------------------------------------------

#define B_      16
#define C_      256
#define H_      64
#define W_      64
#define H1_     62          // after conv1 (VALID)
#define H2_     60          // after conv2 (VALID)
#define H1S_    64          // padded row stride for h1 scratch (float4 aligned)
#define NTILES_ 16          // conv2 spatial tiles (2 x 8)

// Scratch (allocation-free: __device__ globals)
__device__ float g_h1[(size_t)B_ * C_ * H1_ * H1S_];      // ~65 MB, lrelu'd conv1 out, padded width
__device__ float g_ppart[NTILES_ * B_ * C_];              // per-tile spatial partial sums of h2
__device__ float g_p[B_ * C_];                            // pooled [B,C]
__device__ float g_kern[B_ * 9 * C_];                     // per-sample depthwise weights [b][c*9+tap]

__device__ __forceinline__ float lrelu(float v) { return v > 0.f ? v : 0.1f * v; }

// ---------------------------------------------------------------------------
// Direct 3x3 VALID conv, 256->256 channels, fp32.
// Block: 256 threads. Per block: 32 couts x (8 rows x 32 cols) spatial tile.
// Per thread: 8 couts x 4 pixels = 32 accumulators.
// FIRST=true : in = kin (64x64), out = g_h1 (62 rows, stride 64), store+lrelu
// FIRST=false: in = g_h1 (62x62, stride 64), out = g_ppart, lrelu+tile-reduce
// ---------------------------------------------------------------------------
template <bool FIRST>
__global__ __launch_bounds__(256, 2)
void conv3x3_kernel(const float* __restrict__ in_first,
                    const float* __restrict__ w,
                    const float* __restrict__ cbias)
{
    constexpr int HIN  = FIRST ? 64 : 62;
    constexpr int WIN  = FIRST ? 64 : 62;
    constexpr int INS  = 64;                 // input row stride (kin natural 64; h1 padded 64)
    constexpr int HOUT = HIN - 2;
    constexpr int WOUT = WIN - 2;

    __shared__ float sX[8][10][35];          // 8 cin x 10 rows x 34 cols (stride 35: conflict-free)
    __shared__ float sW[32][73];             // 32 cout x (8 cin * 9 taps)
    __shared__ float sRed[64 * 33];          // reduction buffer (REDUCE path)

    const int tid  = threadIdx.x;
    const int cg   = tid >> 6;               // cout group 0..3 (8 couts each)
    const int pg   = tid & 63;               // pixel group 0..63
    const int prow = pg >> 3;                // 0..7
    const int pc   = (pg & 7) << 2;          // 0,4,...,28

    const int tileX = blockIdx.x;            // 2 tiles of 32 cols
    const int tileY = blockIdx.y;            // 8 tiles of 8 rows
    const int z     = blockIdx.z;            // b * 8 + coutBlock
    const int b     = z >> 3;
    const int coutBase = (z & 7) << 5;

    const int orow  = tileY * 8 + prow;
    const int ocol0 = tileX * 32 + pc;
    const int r0 = tileY * 8;
    const int c0 = tileX * 32;

    const float* __restrict__ src = FIRST ? in_first : g_h1;

    float acc[8][4];
#pragma unroll
    for (int co = 0; co < 8; ++co) {
        float bv = cbias[coutBase + cg * 8 + co];
#pragma unroll
        for (int j = 0; j < 4; ++j) acc[co][j] = bv;
    }

    for (int cb = 0; cb < C_; cb += 8) {
        __syncthreads();
        // ---- stage X tile: 8 cin x 10 x 34 = 2720 elements ----
        for (int idx = tid; idx < 2720; idx += 256) {
            int ci  = idx / 340;
            int rem = idx - ci * 340;
            int rr  = rem / 34;
            int cc  = rem - rr * 34;
            int r = r0 + rr, c = c0 + cc;
            float v = 0.f;
            if (r < HIN && c < WIN)
                v = src[((size_t)(b * C_ + cb + ci) * HIN + r) * INS + c];
            sX[ci][rr][cc] = v;
        }
        // ---- stage W tile: 32 cout x 8 cin x 9 ----
        {
            int co_i = tid >> 3, ci_i = tid & 7;
            const float* gw = w + ((size_t)(coutBase + co_i) * C_ + cb + ci_i) * 9;
#pragma unroll
            for (int k = 0; k < 9; ++k) sW[co_i][ci_i * 9 + k] = gw[k];
        }
        __syncthreads();

        // ---- compute ----
#pragma unroll 1
        for (int ci = 0; ci < 8; ++ci) {
#pragma unroll
            for (int ky = 0; ky < 3; ++ky) {
                float xr[6];
#pragma unroll
                for (int j = 0; j < 6; ++j) xr[j] = sX[ci][prow + ky][pc + j];
#pragma unroll
                for (int kx = 0; kx < 3; ++kx) {
#pragma unroll
                    for (int co = 0; co < 8; ++co) {
                        float wv = sW[cg * 8 + co][ci * 9 + ky * 3 + kx];
#pragma unroll
                        for (int j = 0; j < 4; ++j)
                            acc[co][j] = fmaf(xr[kx + j], wv, acc[co][j]);
                    }
                }
            }
        }
    }

    if (FIRST) {
        // store lrelu(acc) to g_h1, padded stride 64, aligned float4
        if (orow < HOUT) {
#pragma unroll
            for (int co = 0; co < 8; ++co) {
                float4 v;
                v.x = lrelu(acc[co][0]); v.y = lrelu(acc[co][1]);
                v.z = lrelu(acc[co][2]); v.w = lrelu(acc[co][3]);
                size_t o = ((size_t)(b * C_ + coutBase + cg * 8 + co) * HOUT + orow) * H1S_ + ocol0;
                *reinterpret_cast<float4*>(&g_h1[o]) = v;
            }
        }
    } else {
        // lrelu + masked spatial partial sum -> g_ppart (deterministic, no atomics)
        float part[8];
#pragma unroll
        for (int co = 0; co < 8; ++co) {
            float s = 0.f;
#pragma unroll
            for (int j = 0; j < 4; ++j) {
                bool valid = (orow < HOUT) && (ocol0 + j < WOUT);
                if (valid) s += lrelu(acc[co][j]);
            }
            part[co] = s;
        }
#pragma unroll
        for (int co = 0; co < 8; ++co)
            sRed[pg * 33 + cg * 8 + co] = part[co];
        __syncthreads();
        if (tid < 32) {
            float s = 0.f;
#pragma unroll 8
            for (int p = 0; p < 64; ++p) s += sRed[p * 33 + tid];
            int t = tileY * 2 + tileX;
            g_ppart[(t * B_ + b) * C_ + coutBase + tid] = s;
        }
    }
}

// ---------------------------------------------------------------------------
// reduce 16 tile partials -> pooled p[b][c] (divide by 60*60)
// ---------------------------------------------------------------------------
__global__ void reduce_p_kernel()
{
    int i = blockIdx.x * 256 + threadIdx.x;   // 0..4095
    float s = 0.f;
#pragma unroll
    for (int t = 0; t < NTILES_; ++t) s += g_ppart[t * (B_ * C_) + i];
    g_p[i] = s * (1.0f / (H2_ * H2_));
}

// ---------------------------------------------------------------------------
// kern[b][o] = sum_c p[b][c] * w3[o][c] + b3[o];   o = c_out*9 + tap
// One warp per o, all 16 batches at once. grid = 2304/8 = 288 blocks x 256thr.
// ---------------------------------------------------------------------------
__global__ void kern_gemm_kernel(const float* __restrict__ w3,
                                 const float* __restrict__ b3)
{
    __shared__ float sp[B_ * C_];             // 16 KB
    const int tid  = threadIdx.x;
    const int warp = tid >> 5;
    const int lane = tid & 31;

    for (int i = tid; i < B_ * C_; i += 256) sp[i] = g_p[i];
    __syncthreads();

    int o = blockIdx.x * 8 + warp;            // 0..2303
    float wreg[8];
#pragma unroll
    for (int i = 0; i < 8; ++i) wreg[i] = w3[(size_t)o * C_ + lane + i * 32];

    float acc[B_];
#pragma unroll
    for (int b = 0; b < B_; ++b) acc[b] = 0.f;
#pragma unroll
    for (int i = 0; i < 8; ++i) {
        int c = lane + i * 32;
        float wv = wreg[i];
#pragma unroll
        for (int b = 0; b < B_; ++b)
            acc[b] = fmaf(wv, sp[b * C_ + c], acc[b]);
    }
#pragma unroll
    for (int off = 16; off > 0; off >>= 1)
#pragma unroll
        for (int b = 0; b < B_; ++b)
            acc[b] += __shfl_xor_sync(0xFFFFFFFFu, acc[b], off);

    if (lane == 0) {
        float bb = b3[o];
#pragma unroll
        for (int b = 0; b < B_; ++b)
            g_kern[b * (9 * C_) + o] = acc[b] + bb;
    }
}

// ---------------------------------------------------------------------------
// Depthwise 3x3 SAME conv with per-(b,c) kernel + bias. One block per (b,c).
// ---------------------------------------------------------------------------
__global__ __launch_bounds__(256)
void dwconv_kernel(const float* __restrict__ x,
                   const float* __restrict__ bias,
                   float* __restrict__ out)
{
    __shared__ float sx[H_ * W_];             // 16 KB
    __shared__ float sk[9];

    const int tid = threadIdx.x;
    const int bc  = blockIdx.x;               // b*256 + c
    const int b   = bc >> 8;
    const int c   = bc & 255;

    const float* xin = x + (size_t)bc * (H_ * W_);
    for (int i = tid; i < (H_ * W_) / 4; i += 256)
        reinterpret_cast<float4*>(sx)[i] = reinterpret_cast<const float4*>(xin)[i];
    if (tid < 9) sk[tid] = g_kern[b * (9 * C_) + c * 9 + tid];
    __syncthreads();

    const float bv = bias[c];
    float k[9];
#pragma unroll
    for (int i = 0; i < 9; ++i) k[i] = sk[i];

    for (int p = tid; p < H_ * W_; p += 256) {
        int y  = p >> 6;
        int xx = p & 63;
        float s = bv;
#pragma unroll
        for (int ky = 0; ky < 3; ++ky) {
            int yy = y + ky - 1;
            if (yy < 0 || yy >= H_) continue;
#pragma unroll
            for (int kx = 0; kx < 3; ++kx) {
                int xc = xx + kx - 1;
                if (xc < 0 || xc >= W_) continue;
                s = fmaf(k[ky * 3 + kx], sx[yy * W_ + xc], s);
            }
        }
        out[(size_t)bc * (H_ * W_) + p] = s;
    }
}

// ---------------------------------------------------------------------------
// Launch. Inputs (metadata order): x, kin, w1, b1, w2, b2, w3, b3, bias
// ---------------------------------------------------------------------------
extern "C" void kernel_launch(void* const* d_in, const int* in_sizes, int n_in,
                              void* d_out, int out_size)
{
    const float* x    = (const float*)d_in[0];
    const float* kin  = (const float*)d_in[1];
    const float* w1   = (const float*)d_in[2];
    const float* b1   = (const float*)d_in[3];
    const float* w2   = (const float*)d_in[4];
    const float* b2   = (const float*)d_in[5];
    const float* w3   = (const float*)d_in[6];
    const float* b3   = (const float*)d_in[7];
    const float* bias = (const float*)d_in[8];
    float* out = (float*)d_out;

    dim3 cgrid(2, 8, B_ * 8);
    conv3x3_kernel<true ><<<cgrid, 256>>>(kin, w1, b1);   // kin -> g_h1 (lrelu'd)
    conv3x3_kernel<false><<<cgrid, 256>>>(nullptr, w2, b2); // g_h1 -> g_ppart
    reduce_p_kernel<<<B_ * C_ / 256, 256>>>();            // g_ppart -> g_p
    kern_gemm_kernel<<<(9 * C_) / 8, 256>>>(w3, b3);      // g_p -> g_kern
    dwconv_kernel<<<B_ * C_, 256>>>(x, bias, out);        // x, g_kern -> out
}